// round 10
// baseline (speedup 1.0000x reference)
#include <cuda_runtime.h>

// ---------------------------------------------------------------------------
// PostGammaDenoise: guided-filter luma smoothing, radius 8, eps 0.005.
// Fully fused single pass. Round 3: 512 threads/block (was 256) at the same
// 114KB smem/block -> 2 blocks/SM still fit (228KB) -> occupancy 24% -> ~50%.
// Phase decompositions re-cut so all phases complete in one task round.
// ---------------------------------------------------------------------------

#define IMG_H 4096
#define IMG_W 4096
#define RAD   8
#define TILE  64
#define REG   (TILE + 4 * RAD)   // 96: Y region
#define ABW   (TILE + 2 * RAD)   // 80: a,b region
#define NT    512

#define SY_STRIDE   (REG + 1)    // 97 floats
#define SH_STRIDE   (ABW + 1)    // 81 float2
#define SAB_STRIDE  (ABW + 1)    // 81 float2
#define SHAB_STRIDE (TILE + 1)   // 65 float2

// Shared-memory layout (floats), with aliasing:
//   [0 .. 15552)        sH   (96 x 81 x float2)  -- phase 1/2; dead after 2
//   [15552 .. 24864)    sY   (96 x 97 floats)    -- phase 0/1; dead after 1
//   [15552 .. 28512)    sAB  (80 x 81 x float2)  -- overwrites sY (phase 2/3)
//   [0 .. 10400)        sHab (80 x 65 x float2)  -- overwrites sH (phase 3/4)
#define OFF_H    0
#define SZ_H     (REG * SH_STRIDE * 2)          // 15552
#define OFF_Y    (OFF_H + SZ_H)                 // 15552
#define OFF_AB   OFF_Y
#define SZ_AB    (ABW * SAB_STRIDE * 2)         // 12960
#define OFF_HAB  0
#define SMEM_FLOATS (OFF_AB + SZ_AB)            // 28512
#define SMEM_BYTES  (SMEM_FLOATS * 4)           // 114048 -> 2 blocks/SM

__device__ __forceinline__ int mirror_lo_hi(int v, int n) {
    v = (v < 0) ? -v : v;
    v = (v >= n) ? (2 * n - 2 - v) : v;
    return v;
}

__global__ __launch_bounds__(NT, 2)
void PostGammaDenoise_kernel(const float* __restrict__ x,
                             float* __restrict__ out) {
    extern __shared__ float sm[];
    float*  sY   = sm + OFF_Y;
    float2* sH   = (float2*)(sm + OFF_H);
    float2* sAB  = (float2*)(sm + OFF_AB);
    float2* sHab = (float2*)(sm + OFF_HAB);

    const int tx0 = blockIdx.x * TILE;
    const int ty0 = blockIdx.y * TILE;
    const int tid = threadIdx.x;
    const float inv289 = 1.0f / 289.0f;

    // ------------------------------------------------------------ Phase 0
    // Load 96x96 luma region with reflect mirroring. 9216/512 = 18 per thread.
    #pragma unroll 3
    for (int i = tid; i < REG * REG; i += NT) {
        int r = i / REG, c = i % REG;
        int gy = mirror_lo_hi(ty0 - 2 * RAD + r, IMG_H);
        int gx = mirror_lo_hi(tx0 - 2 * RAD + c, IMG_W);
        const float* p = x + ((size_t)gy * IMG_W + gx) * 3;
        float Y = 0.2126f * p[0] + 0.7152f * p[1] + 0.0722f * p[2];
        sY[r * SY_STRIDE + c] = Y;
    }
    __syncthreads();

    // ------------------------------------------------------------ Phase 1
    // Horizontal 17-tap raw sums of (Y, Y^2): 96 rows x 80 cols.
    // 96 rows x 5 segments of 16 cols = 480 tasks (one round on 512 threads).
    if (tid < REG * 5) {
        int row = tid % REG;
        int c0  = (tid / REG) * 16;
        const float* yr = sY + row * SY_STRIDE;
        float s0 = 0.f, s1 = 0.f;
        #pragma unroll
        for (int k = 0; k < 17; k++) {
            float v = yr[c0 + k];
            s0 += v; s1 += v * v;
        }
        int c = c0;
        for (;;) {
            sH[row * SH_STRIDE + c] = make_float2(s0, s1);
            if (++c == c0 + 16) break;
            float vin  = yr[c + 16];
            float vout = yr[c - 1];
            s0 += vin - vout;
            s1 += vin * vin - vout * vout;
        }
    }
    __syncthreads();

    // ------------------------------------------------------------ Phase 2
    // Vertical 17-tap sums -> mean_I, mean_II -> (a, b): 80 x 80.
    // 80 cols x 5 segments of 16 rows = 400 tasks. Writes alias dead sY.
    if (tid < ABW * 5) {
        int col = tid % ABW;
        int r0  = (tid / ABW) * 16;
        float s0 = 0.f, s1 = 0.f;
        #pragma unroll
        for (int k = 0; k < 17; k++) {
            float2 v = sH[(r0 + k) * SH_STRIDE + col];
            s0 += v.x; s1 += v.y;
        }
        int r = r0;
        for (;;) {
            float mI  = s0 * inv289;
            float mII = s1 * inv289;
            float var = mII - mI * mI;
            float a   = var / (var + 0.005f);
            float b   = mI * (1.0f - a);
            sAB[r * SAB_STRIDE + col] = make_float2(a, b);
            if (++r == r0 + 16) break;
            float2 vin  = sH[(r + 16) * SH_STRIDE + col];
            float2 vout = sH[(r - 1) * SH_STRIDE + col];
            s0 += vin.x - vout.x;
            s1 += vin.y - vout.y;
        }
    }
    __syncthreads();

    // ------------------------------------------------------------ Phase 3
    // Horizontal 17-tap raw sums of (a, b): 80 rows x 64 cols.
    // 80 rows x 4 segments of 16 cols = 320 tasks. Writes alias dead sH.
    if (tid < ABW * 4) {
        int row = tid % ABW;
        int c0  = (tid / ABW) * 16;
        const float2* ar = sAB + row * SAB_STRIDE;
        float s0 = 0.f, s1 = 0.f;
        #pragma unroll
        for (int k = 0; k < 17; k++) {
            float2 v = ar[c0 + k];
            s0 += v.x; s1 += v.y;
        }
        int c = c0;
        for (;;) {
            sHab[row * SHAB_STRIDE + c] = make_float2(s0, s1);
            if (++c == c0 + 16) break;
            float2 vin  = ar[c + 16];
            float2 vout = ar[c - 1];
            s0 += vin.x - vout.x;
            s1 += vin.y - vout.y;
        }
    }
    __syncthreads();

    // ------------------------------------------------------------ Phase 4
    // Vertical 17-tap sums -> mean_a, mean_b; recombine; store.
    // 64 cols x 8 segments of 8 rows = 512 tasks (all threads busy).
    {
        int col = tid % TILE;
        int r0  = (tid / TILE) * 8;
        float s0 = 0.f, s1 = 0.f;
        #pragma unroll
        for (int k = 0; k < 17; k++) {
            float2 v = sHab[(r0 + k) * SHAB_STRIDE + col];
            s0 += v.x; s1 += v.y;
        }
        int r = r0;
        for (;;) {
            float mA = s0 * inv289;
            float mB = s1 * inv289;
            size_t gidx = ((size_t)(ty0 + r) * IMG_W + (tx0 + col)) * 3;
            const float* p = x + gidx;
            float xr = p[0], xg = p[1], xb = p[2];
            float Y  = 0.2126f * xr + 0.7152f * xg + 0.0722f * xb;
            float Ys = mA * Y + mB;
            float scale = Ys / fmaxf(Y, 1e-6f);
            float* q = out + gidx;
            q[0] = fminf(fmaxf(xr * scale, 0.f), 1.f);
            q[1] = fminf(fmaxf(xg * scale, 0.f), 1.f);
            q[2] = fminf(fmaxf(xb * scale, 0.f), 1.f);
            if (++r == r0 + 8) break;
            float2 vin  = sHab[(r + 16) * SHAB_STRIDE + col];
            float2 vout = sHab[(r - 1) * SHAB_STRIDE + col];
            s0 += vin.x - vout.x;
            s1 += vin.y - vout.y;
        }
    }
}

extern "C" void kernel_launch(void* const* d_in, const int* in_sizes, int n_in,
                              void* d_out, int out_size) {
    const float* x = (const float*)d_in[0];
    float* out = (float*)d_out;

    cudaFuncSetAttribute(PostGammaDenoise_kernel,
                         cudaFuncAttributeMaxDynamicSharedMemorySize,
                         SMEM_BYTES);

    dim3 grid(IMG_W / TILE, IMG_H / TILE);  // 64 x 64 = 4096 tiles
    PostGammaDenoise_kernel<<<grid, NT, SMEM_BYTES>>>(x, out);
}

// round 14
// speedup vs baseline: 1.0022x; 1.0022x over previous
#include <cuda_runtime.h>

// ---------------------------------------------------------------------------
// PostGammaDenoise: guided-filter luma smoothing, radius 8, eps 0.005.
// Fully fused single pass. Round 3: 512 threads/block (was 256) at the same
// 114KB smem/block -> 2 blocks/SM still fit (228KB) -> occupancy 24% -> ~50%.
// Phase decompositions re-cut so all phases complete in one task round.
// ---------------------------------------------------------------------------

#define IMG_H 4096
#define IMG_W 4096
#define RAD   8
#define TILE  64
#define REG   (TILE + 4 * RAD)   // 96: Y region
#define ABW   (TILE + 2 * RAD)   // 80: a,b region
#define NT    512

#define SY_STRIDE   (REG + 1)    // 97 floats
#define SH_STRIDE   (ABW + 1)    // 81 float2
#define SAB_STRIDE  (ABW + 1)    // 81 float2
#define SHAB_STRIDE (TILE + 1)   // 65 float2

// Shared-memory layout (floats), with aliasing:
//   [0 .. 15552)        sH   (96 x 81 x float2)  -- phase 1/2; dead after 2
//   [15552 .. 24864)    sY   (96 x 97 floats)    -- phase 0/1; dead after 1
//   [15552 .. 28512)    sAB  (80 x 81 x float2)  -- overwrites sY (phase 2/3)
//   [0 .. 10400)        sHab (80 x 65 x float2)  -- overwrites sH (phase 3/4)
#define OFF_H    0
#define SZ_H     (REG * SH_STRIDE * 2)          // 15552
#define OFF_Y    (OFF_H + SZ_H)                 // 15552
#define OFF_AB   OFF_Y
#define SZ_AB    (ABW * SAB_STRIDE * 2)         // 12960
#define OFF_HAB  0
#define SMEM_FLOATS (OFF_AB + SZ_AB)            // 28512
#define SMEM_BYTES  (SMEM_FLOATS * 4)           // 114048 -> 2 blocks/SM

__device__ __forceinline__ int mirror_lo_hi(int v, int n) {
    v = (v < 0) ? -v : v;
    v = (v >= n) ? (2 * n - 2 - v) : v;
    return v;
}

__global__ __launch_bounds__(NT, 2)
void PostGammaDenoise_kernel(const float* __restrict__ x,
                             float* __restrict__ out) {
    extern __shared__ float sm[];
    float*  sY   = sm + OFF_Y;
    float2* sH   = (float2*)(sm + OFF_H);
    float2* sAB  = (float2*)(sm + OFF_AB);
    float2* sHab = (float2*)(sm + OFF_HAB);

    const int tx0 = blockIdx.x * TILE;
    const int ty0 = blockIdx.y * TILE;
    const int tid = threadIdx.x;
    const float inv289 = 1.0f / 289.0f;

    // ------------------------------------------------------------ Phase 0
    // Load 96x96 luma region with reflect mirroring. 9216/512 = 18 per thread.
    #pragma unroll 3
    for (int i = tid; i < REG * REG; i += NT) {
        int r = i / REG, c = i % REG;
        int gy = mirror_lo_hi(ty0 - 2 * RAD + r, IMG_H);
        int gx = mirror_lo_hi(tx0 - 2 * RAD + c, IMG_W);
        const float* p = x + ((size_t)gy * IMG_W + gx) * 3;
        float Y = 0.2126f * p[0] + 0.7152f * p[1] + 0.0722f * p[2];
        sY[r * SY_STRIDE + c] = Y;
    }
    __syncthreads();

    // ------------------------------------------------------------ Phase 1
    // Horizontal 17-tap raw sums of (Y, Y^2): 96 rows x 80 cols.
    // 96 rows x 5 segments of 16 cols = 480 tasks (one round on 512 threads).
    if (tid < REG * 5) {
        int row = tid % REG;
        int c0  = (tid / REG) * 16;
        const float* yr = sY + row * SY_STRIDE;
        float s0 = 0.f, s1 = 0.f;
        #pragma unroll
        for (int k = 0; k < 17; k++) {
            float v = yr[c0 + k];
            s0 += v; s1 += v * v;
        }
        int c = c0;
        for (;;) {
            sH[row * SH_STRIDE + c] = make_float2(s0, s1);
            if (++c == c0 + 16) break;
            float vin  = yr[c + 16];
            float vout = yr[c - 1];
            s0 += vin - vout;
            s1 += vin * vin - vout * vout;
        }
    }
    __syncthreads();

    // ------------------------------------------------------------ Phase 2
    // Vertical 17-tap sums -> mean_I, mean_II -> (a, b): 80 x 80.
    // 80 cols x 5 segments of 16 rows = 400 tasks. Writes alias dead sY.
    if (tid < ABW * 5) {
        int col = tid % ABW;
        int r0  = (tid / ABW) * 16;
        float s0 = 0.f, s1 = 0.f;
        #pragma unroll
        for (int k = 0; k < 17; k++) {
            float2 v = sH[(r0 + k) * SH_STRIDE + col];
            s0 += v.x; s1 += v.y;
        }
        int r = r0;
        for (;;) {
            float mI  = s0 * inv289;
            float mII = s1 * inv289;
            float var = mII - mI * mI;
            float a   = var / (var + 0.005f);
            float b   = mI * (1.0f - a);
            sAB[r * SAB_STRIDE + col] = make_float2(a, b);
            if (++r == r0 + 16) break;
            float2 vin  = sH[(r + 16) * SH_STRIDE + col];
            float2 vout = sH[(r - 1) * SH_STRIDE + col];
            s0 += vin.x - vout.x;
            s1 += vin.y - vout.y;
        }
    }
    __syncthreads();

    // ------------------------------------------------------------ Phase 3
    // Horizontal 17-tap raw sums of (a, b): 80 rows x 64 cols.
    // 80 rows x 4 segments of 16 cols = 320 tasks. Writes alias dead sH.
    if (tid < ABW * 4) {
        int row = tid % ABW;
        int c0  = (tid / ABW) * 16;
        const float2* ar = sAB + row * SAB_STRIDE;
        float s0 = 0.f, s1 = 0.f;
        #pragma unroll
        for (int k = 0; k < 17; k++) {
            float2 v = ar[c0 + k];
            s0 += v.x; s1 += v.y;
        }
        int c = c0;
        for (;;) {
            sHab[row * SHAB_STRIDE + c] = make_float2(s0, s1);
            if (++c == c0 + 16) break;
            float2 vin  = ar[c + 16];
            float2 vout = ar[c - 1];
            s0 += vin.x - vout.x;
            s1 += vin.y - vout.y;
        }
    }
    __syncthreads();

    // ------------------------------------------------------------ Phase 4
    // Vertical 17-tap sums -> mean_a, mean_b; recombine; store.
    // 64 cols x 8 segments of 8 rows = 512 tasks (all threads busy).
    {
        int col = tid % TILE;
        int r0  = (tid / TILE) * 8;
        float s0 = 0.f, s1 = 0.f;
        #pragma unroll
        for (int k = 0; k < 17; k++) {
            float2 v = sHab[(r0 + k) * SHAB_STRIDE + col];
            s0 += v.x; s1 += v.y;
        }
        int r = r0;
        for (;;) {
            float mA = s0 * inv289;
            float mB = s1 * inv289;
            size_t gidx = ((size_t)(ty0 + r) * IMG_W + (tx0 + col)) * 3;
            const float* p = x + gidx;
            float xr = p[0], xg = p[1], xb = p[2];
            float Y  = 0.2126f * xr + 0.7152f * xg + 0.0722f * xb;
            float Ys = mA * Y + mB;
            float scale = Ys / fmaxf(Y, 1e-6f);
            float* q = out + gidx;
            q[0] = fminf(fmaxf(xr * scale, 0.f), 1.f);
            q[1] = fminf(fmaxf(xg * scale, 0.f), 1.f);
            q[2] = fminf(fmaxf(xb * scale, 0.f), 1.f);
            if (++r == r0 + 8) break;
            float2 vin  = sHab[(r + 16) * SHAB_STRIDE + col];
            float2 vout = sHab[(r - 1) * SHAB_STRIDE + col];
            s0 += vin.x - vout.x;
            s1 += vin.y - vout.y;
        }
    }
}

extern "C" void kernel_launch(void* const* d_in, const int* in_sizes, int n_in,
                              void* d_out, int out_size) {
    const float* x = (const float*)d_in[0];
    float* out = (float*)d_out;

    cudaFuncSetAttribute(PostGammaDenoise_kernel,
                         cudaFuncAttributeMaxDynamicSharedMemorySize,
                         SMEM_BYTES);

    dim3 grid(IMG_W / TILE, IMG_H / TILE);  // 64 x 64 = 4096 tiles
    PostGammaDenoise_kernel<<<grid, NT, SMEM_BYTES>>>(x, out);
}